// round 17
// baseline (speedup 1.0000x reference)
#include <cuda_runtime.h>
#include <cstdint>

#define BATCH 32
#define IN_H  128
#define IN_W  512
#define CHAN  32
#define OUT_H 64
#define OUT_W 256

// Warp-autonomous gathers + TMA bulk store.
// Each warp owns 8 consecutive output points (one contiguous 1KB output
// segment). lanes 0..7 compute params -> smem; 8 threads/point gather 4
// pixels (LDG.128), blend, stage result in smem; lane 0 issues ONE
// cp.async.bulk (smem -> gmem, 1024B) on the TMA pipe -> store wavefronts
// leave the L1/LSU path. No __syncthreads anywhere.
// Block = 256 thr = 8 warps = 64 points. Grid = 8192 blocks.

struct PParam {
    float    wA, wB, wC, wD;
    unsigned iA, iB, iC, iD;   // pixel index * 8 (float4 units), without cg
};

__global__ void __launch_bounds__(256, 8)
stn_bilinear_kernel(const float* __restrict__ image,
                    const float* __restrict__ theta,
                    float* __restrict__ out)
{
    __shared__ PParam sp[64];
    __shared__ __align__(16) float4 stage[8][64];   // 1KB per warp

    const unsigned tid  = threadIdx.x;
    const unsigned lane = tid & 31u;
    const unsigned w    = tid >> 5;                    // warp 0..7
    const unsigned base = (blockIdx.x * 8u + w) * 8u;  // warp's first point

    // ---- lanes 0..7: params for the warp's 8 points ----
    if (lane < 8u) {
        const unsigned n  = base + lane;
        const unsigned wx = n & 255u;          // OUT_W = 256
        const unsigned r  = n >> 8;
        const unsigned hy = r & 63u;           // OUT_H = 64
        const unsigned b  = r >> 6;

        const float xg = (float)wx * (2.0f / 255.0f) - 1.0f;
        const float yg = (float)hy * (2.0f / 63.0f) - 1.0f;

        // theta[b] 2x3; reference hack: zero row 1 of batch 0, row 0 of batch 1
        const float* th = theta + b * 6u;
        float t00 = __ldg(th + 0), t01 = __ldg(th + 1), t02 = __ldg(th + 2);
        float t10 = __ldg(th + 3), t11 = __ldg(th + 4), t12 = __ldg(th + 5);
        if (b == 0u) { t10 = 0.0f; t11 = 0.0f; t12 = 0.0f; }
        if (b == 1u) { t00 = 0.0f; t01 = 0.0f; t02 = 0.0f; }

        float cx = t00 * xg + t01 * yg + t02;
        float cy = t10 * xg + t11 * yg + t12;

        float x = 0.5f * (cx + 1.0f) * (float)IN_W;   // uses W, not W-1
        float y = 0.5f * (cy + 1.0f) * (float)IN_H;

        int x0 = (int)x;                              // trunc toward zero
        int y0 = (int)y;
        int x1 = x0 + 1;
        int y1 = y0 + 1;
        x0 = min(max(x0, 0), IN_W - 1);               // clip BEFORE weights
        x1 = min(max(x1, 0), IN_W - 1);
        y0 = min(max(y0, 0), IN_H - 1);
        y1 = min(max(y1, 0), IN_H - 1);

        float x0f = (float)x0, x1f = (float)x1;
        float y0f = (float)y0, y1f = (float)y1;

        PParam pp;
        pp.wA = (x1f - x) * (y1f - y);
        pp.wB = (x1f - x) * (y - y0f);
        pp.wC = (x - x0f) * (y1f - y);
        pp.wD = (x - x0f) * (y - y0f);

        const unsigned basePix = b * (unsigned)(IN_H * IN_W);
        const unsigned row0 = basePix + (unsigned)y0 * (unsigned)IN_W;
        const unsigned row1 = basePix + (unsigned)y1 * (unsigned)IN_W;
        pp.iA = (row0 + (unsigned)x0) << 3;
        pp.iB = (row1 + (unsigned)x0) << 3;
        pp.iC = (row0 + (unsigned)x1) << 3;
        pp.iD = (row1 + (unsigned)x1) << 3;

        sp[w * 8u + lane] = pp;
    }
    __syncwarp();

    // ---- 8 threads per point, 2 points per thread; results -> smem ----
    const unsigned cg = lane & 7u;
    const unsigned q  = lane >> 3;       // 0..3

    const float4* __restrict__ img4 = (const float4*)image;

    #pragma unroll
    for (int half = 0; half < 2; ++half) {
        const unsigned pi = (unsigned)half * 4u + q;      // 0..7 within warp
        const PParam pp = sp[w * 8u + pi];

        float4 pA = __ldg(img4 + (pp.iA + cg));
        float4 pB = __ldg(img4 + (pp.iB + cg));
        float4 pC = __ldg(img4 + (pp.iC + cg));
        float4 pD = __ldg(img4 + (pp.iD + cg));

        float4 res;
        res.x = pA.x * pp.wA + pB.x * pp.wB + pC.x * pp.wC + pD.x * pp.wD;
        res.y = pA.y * pp.wA + pB.y * pp.wB + pC.y * pp.wC + pD.y * pp.wD;
        res.z = pA.z * pp.wA + pB.z * pp.wB + pC.z * pp.wC + pD.z * pp.wD;
        res.w = pA.w * pp.wA + pB.w * pp.wB + pC.w * pp.wC + pD.w * pp.wD;

        stage[w][pi * 8u + cg] = res;      // STS.128 (smem bank path)
    }
    __syncwarp();

    // generic-proxy smem writes must be visible to the async (TMA) proxy
    asm volatile("fence.proxy.async.shared::cta;" ::: "memory");

    if (lane == 0u) {
        // warp's 8 points -> contiguous 1024B at out + base*32 floats
        uint32_t saddr;
        asm("{ .reg .u64 t; cvta.to.shared.u64 t, %1; cvt.u32.u64 %0, t; }"
            : "=r"(saddr) : "l"(&stage[w][0]));
        const float* dst = out + (size_t)base * 32u;
        asm volatile(
            "cp.async.bulk.global.shared::cta.bulk_group [%0], [%1], 1024;"
            :: "l"(dst), "r"(saddr) : "memory");
        asm volatile("cp.async.bulk.commit_group;" ::: "memory");
        asm volatile("cp.async.bulk.wait_group 0;" ::: "memory");
    }
}

extern "C" void kernel_launch(void* const* d_in, const int* in_sizes, int n_in,
                              void* d_out, int out_size)
{
    const float* image = (const float*)d_in[0];
    const float* theta = (const float*)d_in[1];
    float*       out   = (float*)d_out;

    stn_bilinear_kernel<<<8192, 256>>>(image, theta, out);
}